// round 16
// baseline (speedup 1.0000x reference)
#include <cuda_runtime.h>
#include <cuda_fp16.h>

#define N_NODES 100000
#define N_EDGES 1600000
#define N_GRAPHS 512
#define HID 128

// Scratch (allocation-free rule: __device__ globals; referenced only from device code)
__device__ __half2 g_Ah[(size_t)N_NODES * 64]; // GEMM output (UNscaled), fp16
__device__ __half2 g_Bh[(size_t)N_NODES * 64]; // layer output, fp16
__device__ float g_dis[N_NODES];               // (deg+1)^{-1/2}
__device__ int   g_degi[N_NODES];
__device__ int   g_rowptr[N_NODES];
__device__ int   g_cur[N_NODES];
__device__ int   g_adj[N_EDGES];               // packed CSR (order-free slabs)
__device__ int   g_start[N_GRAPHS];
__device__ int   g_end[N_GRAPHS];
__device__ int   g_total;

// ---------------- zero counters + graph boundaries (fused) ----------------
__global__ void k_zero(const int* __restrict__ batch) {
    int i = blockIdx.x * blockDim.x + threadIdx.x;
    if (i < N_NODES) {
        g_degi[i] = 0;
        unsigned g = (unsigned)batch[i];
        if (g < N_GRAPHS) {
            if (i == 0 || batch[i - 1] != (int)g) g_start[g] = i;
            if (i == N_NODES - 1 || batch[i + 1] != (int)g) g_end[g] = i + 1;
        }
    }
    if (i == 0) g_total = 0;
}

// ---------------- in-degree count over dst ----------------
__global__ void k_deg(const int* __restrict__ dst) {
    int e = blockIdx.x * blockDim.x + threadIdx.x;
    if (e < N_EDGES) {
        unsigned d = (unsigned)dst[e];
        if (d < N_NODES) atomicAdd(&g_degi[d], 1);
    }
}

// ---------------- parallel slab reservation ----------------
__global__ void __launch_bounds__(256) k_build() {
    __shared__ int s[256];
    __shared__ int s_base;
    int t = threadIdx.x;
    int i = blockIdx.x * 256 + t;
    int d = (i < N_NODES) ? g_degi[i] : 0;
    s[t] = d;
    __syncthreads();
    #pragma unroll
    for (int o = 1; o < 256; o <<= 1) {
        int v = (t >= o) ? s[t - o] : 0;
        __syncthreads();
        s[t] += v;
        __syncthreads();
    }
    if (t == 255) s_base = atomicAdd(&g_total, s[255]);
    __syncthreads();
    if (i < N_NODES) {
        int start = s_base + s[t] - d;
        g_rowptr[i] = start;
        g_cur[i] = start;
        g_dis[i] = rsqrtf((float)(d + 1));   // +1 self loop
    }
}

// ---------------- fill adjacency (src grouped by dst) ----------------
__global__ void k_fill(const int* __restrict__ src,
                       const int* __restrict__ dst) {
    int e = blockIdx.x * blockDim.x + threadIdx.x;
    if (e < N_EDGES) {
        unsigned d = (unsigned)dst[e];
        unsigned sv = (unsigned)src[e];
        if (d < N_NODES && sv < N_NODES) {
            int pos = atomicAdd(&g_cur[d], 1);
            g_adj[pos] = (int)sv;
        }
    }
}

// ---------------- TF32 tensor-core GEMM: g_Ah[row] = fp16(In[row]@W) (no dis) --------
#define A_STRIDE 132
#define W_STRIDE 136
#define GEMM_SMEM ((64 * A_STRIDE + 128 * W_STRIDE) * 4)

__device__ __forceinline__ float tf32r(float x) {
    float y;
    asm("cvt.rna.tf32.f32 %0, %1;" : "=f"(y) : "f"(x));
    return y;
}

__global__ void __launch_bounds__(256) k_gemm_tc(const float* __restrict__ X,
                                                 const float* __restrict__ W,
                                                 int useB) {
    extern __shared__ float smem[];
    float* sA = smem;                    // [64][132]
    float* sW = smem + 64 * A_STRIDE;    // [128][136]

    const int tid = threadIdx.x;
    const int lane = tid & 31;
    const int wid = tid >> 5;
    const int warpM = wid >> 2;          // 0..1
    const int warpN = wid & 3;           // 0..3
    const int g = lane >> 2;             // 0..7
    const int t = lane & 3;              // 0..3
    const int rowBase = blockIdx.x * 64;

    #pragma unroll
    for (int l = tid; l < 2048; l += 256) {
        int r = l >> 5, c4 = (l & 31) * 4;
        int row = rowBase + r;
        float4 v = make_float4(0.f, 0.f, 0.f, 0.f);
        if (row < N_NODES) {
            if (useB) {
                uint2 u = ((const uint2*)g_Bh)[(size_t)row * 32 + (l & 31)];
                float2 f0 = __half22float2(*(__half2*)&u.x);
                float2 f1 = __half22float2(*(__half2*)&u.y);
                v = make_float4(f0.x, f0.y, f1.x, f1.y);
            } else {
                v = *(const float4*)(X + (size_t)row * 128 + c4);
            }
        }
        float* p = &sA[r * A_STRIDE + c4];
        p[0] = tf32r(v.x); p[1] = tf32r(v.y); p[2] = tf32r(v.z); p[3] = tf32r(v.w);
    }
    #pragma unroll
    for (int l = tid; l < 4096; l += 256) {
        int r = l >> 5, c4 = (l & 31) * 4;
        float4 v = *(const float4*)(W + (size_t)r * 128 + c4);
        float* p = &sW[r * W_STRIDE + c4];
        p[0] = tf32r(v.x); p[1] = tf32r(v.y); p[2] = tf32r(v.z); p[3] = tf32r(v.w);
    }
    __syncthreads();

    float acc[2][4][4];
    #pragma unroll
    for (int mi = 0; mi < 2; mi++)
        #pragma unroll
        for (int ni = 0; ni < 4; ni++)
            #pragma unroll
            for (int k = 0; k < 4; k++) acc[mi][ni][k] = 0.f;

    #pragma unroll
    for (int k0 = 0; k0 < 128; k0 += 8) {
        unsigned a[2][4];
        #pragma unroll
        for (int mi = 0; mi < 2; mi++) {
            int rlo = (warpM * 32 + mi * 16 + g) * A_STRIDE;
            int rhi = rlo + 8 * A_STRIDE;
            a[mi][0] = __float_as_uint(sA[rlo + k0 + t]);
            a[mi][1] = __float_as_uint(sA[rhi + k0 + t]);
            a[mi][2] = __float_as_uint(sA[rlo + k0 + t + 4]);
            a[mi][3] = __float_as_uint(sA[rhi + k0 + t + 4]);
        }
        #pragma unroll
        for (int ni = 0; ni < 4; ni++) {
            int n = warpN * 32 + ni * 8 + g;
            unsigned b0 = __float_as_uint(sW[(k0 + t) * W_STRIDE + n]);
            unsigned b1 = __float_as_uint(sW[(k0 + t + 4) * W_STRIDE + n]);
            #pragma unroll
            for (int mi = 0; mi < 2; mi++) {
                asm volatile(
                    "mma.sync.aligned.m16n8k8.row.col.f32.tf32.tf32.f32 "
                    "{%0,%1,%2,%3}, {%4,%5,%6,%7}, {%8,%9}, {%0,%1,%2,%3};"
                    : "+f"(acc[mi][ni][0]), "+f"(acc[mi][ni][1]),
                      "+f"(acc[mi][ni][2]), "+f"(acc[mi][ni][3])
                    : "r"(a[mi][0]), "r"(a[mi][1]), "r"(a[mi][2]), "r"(a[mi][3]),
                      "r"(b0), "r"(b1));
            }
        }
    }

    // ---- epilogue: convert to fp16 (unscaled), store half2 ----
    #pragma unroll
    for (int mi = 0; mi < 2; mi++) {
        int rlo = rowBase + warpM * 32 + mi * 16 + g;
        int rhi = rlo + 8;
        #pragma unroll
        for (int ni = 0; ni < 4; ni++) {
            int h2idx = warpN * 16 + ni * 4 + t;
            if (rlo < N_NODES)
                g_Ah[(size_t)rlo * 64 + h2idx] =
                    __floats2half2_rn(acc[mi][ni][0], acc[mi][ni][1]);
            if (rhi < N_NODES)
                g_Ah[(size_t)rhi * 64 + h2idx] =
                    __floats2half2_rn(acc[mi][ni][2], acc[mi][ni][3]);
        }
    }
}

// ---------------- gather + finalize: one warp per dst node (no atomics) ----------------
// g_Bh[d] = fp16(relu(dis_d * (dis_d*h_d + sum_s dis_s*h_s) + bias)), fp32 accumulate.
// 8-deep unroll: 8 independent row-loads in flight per warp against ~250cyc L2 latency.
__device__ __forceinline__ float4 h2f4(uint2 u) {
    float2 f0 = __half22float2(*(__half2*)&u.x);
    float2 f1 = __half22float2(*(__half2*)&u.y);
    return make_float4(f0.x, f0.y, f1.x, f1.y);
}

__device__ __forceinline__ void fma4(float4& a, float4 v, float d) {
    a.x = fmaf(v.x, d, a.x); a.y = fmaf(v.y, d, a.y);
    a.z = fmaf(v.z, d, a.z); a.w = fmaf(v.w, d, a.w);
}

__global__ void k_gather(const float* __restrict__ bias) {
    int node = (blockIdx.x * blockDim.x + threadIdx.x) >> 5;
    if (node >= N_NODES) return;
    const int lane = threadIdx.x & 31;
    const uint2* A = (const uint2*)g_Ah;
    const float sc = g_dis[node];

    float4 self = h2f4(A[(size_t)node * 32 + lane]);
    float4 acc[8];
    acc[0] = make_float4(self.x * sc, self.y * sc, self.z * sc, self.w * sc);
    #pragma unroll
    for (int j = 1; j < 8; j++) acc[j] = make_float4(0.f, 0.f, 0.f, 0.f);

    int r0 = g_rowptr[node];
    int r1 = r0 + g_degi[node];
    int i = r0;
    for (; i + 7 < r1; i += 8) {
        int   s[8];
        float d[8];
        float4 v[8];
        #pragma unroll
        for (int j = 0; j < 8; j++) s[j] = g_adj[i + j];
        #pragma unroll
        for (int j = 0; j < 8; j++) d[j] = g_dis[s[j]];
        #pragma unroll
        for (int j = 0; j < 8; j++) v[j] = h2f4(A[(size_t)s[j] * 32 + lane]);
        #pragma unroll
        for (int j = 0; j < 8; j++) fma4(acc[j], v[j], d[j]);
    }
    if (i + 3 < r1) {
        int   s[4];
        float d[4];
        float4 v[4];
        #pragma unroll
        for (int j = 0; j < 4; j++) s[j] = g_adj[i + j];
        #pragma unroll
        for (int j = 0; j < 4; j++) d[j] = g_dis[s[j]];
        #pragma unroll
        for (int j = 0; j < 4; j++) v[j] = h2f4(A[(size_t)s[j] * 32 + lane]);
        #pragma unroll
        for (int j = 0; j < 4; j++) fma4(acc[j], v[j], d[j]);
        i += 4;
    }
    for (; i < r1; i++) {
        int s0 = g_adj[i];
        float d0 = g_dis[s0];
        float4 v0 = h2f4(A[(size_t)s0 * 32 + lane]);
        fma4(acc[0], v0, d0);
    }
    #pragma unroll
    for (int j = 1; j < 8; j++) {
        acc[0].x += acc[j].x; acc[0].y += acc[j].y;
        acc[0].z += acc[j].z; acc[0].w += acc[j].w;
    }

    float4 bi = ((const float4*)bias)[lane];
    float rx = fmaxf(fmaf(acc[0].x, sc, bi.x), 0.f);
    float ry = fmaxf(fmaf(acc[0].y, sc, bi.y), 0.f);
    float rz = fmaxf(fmaf(acc[0].z, sc, bi.z), 0.f);
    float rw = fmaxf(fmaf(acc[0].w, sc, bi.w), 0.f);

    uint2 o;
    *(__half2*)&o.x = __floats2half2_rn(rx, ry);
    *(__half2*)&o.y = __floats2half2_rn(rz, rw);
    ((uint2*)g_Bh)[(size_t)node * 32 + lane] = o;
}

// ---------------- fused pool + head: block per graph ----------------
__global__ void __launch_bounds__(128) k_poolhead(const float* __restrict__ Wp,
                                                  const float* __restrict__ bp,
                                                  float* __restrict__ out) {
    __shared__ float sred[128];
    int g = blockIdx.x;
    int c = threadIdx.x;
    int s = g_start[g], e = g_end[g];
    const __half* Bh = (const __half*)g_Bh;
    float sum = 0.f;
    for (int r = s; r < e; r++)
        sum += __half2float(Bh[(size_t)r * 128 + c]);
    sred[c] = sum * Wp[c];
    __syncthreads();
    #pragma unroll
    for (int o = 64; o; o >>= 1) {
        if (c < o) sred[c] += sred[c + o];
        __syncthreads();
    }
    if (c == 0) {
        float cnt = (float)(e - s);
        out[g] = sred[0] / fmaxf(cnt, 1.0f) + bp[0];
    }
}

extern "C" void kernel_launch(void* const* d_in, const int* in_sizes, int n_in,
                              void* d_out, int out_size) {
    const float* x     = (const float*)d_in[0];
    const int*   ei    = (const int*)d_in[1];      // [2, E] int32
    const int*   batch = (const int*)d_in[2];      // int32
    const float* W1    = (const float*)d_in[3];
    const float* b1    = (const float*)d_in[4];
    const float* W2    = (const float*)d_in[5];
    const float* b2    = (const float*)d_in[6];
    const float* Wp    = (const float*)d_in[7];
    const float* bp    = (const float*)d_in[8];
    float* out = (float*)d_out;

    const int* src = ei;
    const int* dst = ei + N_EDGES;

    const int nodeBlocks   = (N_NODES + 255) / 256;
    const int edgeBlocks   = (N_EDGES + 255) / 256;
    const int gemmBlocks   = (N_NODES + 63) / 64;
    const int gatherBlocks = (N_NODES * 32 + 255) / 256;

    // One-time infra (created on first call, before graph capture)
    static cudaStream_t s2 = nullptr;
    static cudaEvent_t evFork = nullptr, evJoin = nullptr;
    static bool initDone = false;
    if (!initDone) {
        cudaFuncSetAttribute(k_gemm_tc, cudaFuncAttributeMaxDynamicSharedMemorySize,
                             GEMM_SMEM);
        cudaStreamCreateWithFlags(&s2, cudaStreamNonBlocking);
        cudaEventCreateWithFlags(&evFork, cudaEventDisableTiming);
        cudaEventCreateWithFlags(&evJoin, cudaEventDisableTiming);
        initDone = true;
    }

    // Fork: GEMM1 (independent of CSR build — dis applied in gather)
    cudaEventRecord(evFork, 0);
    cudaStreamWaitEvent(s2, evFork, 0);
    k_gemm_tc<<<gemmBlocks, 256, GEMM_SMEM, s2>>>(x, W1, 0);
    cudaEventRecord(evJoin, s2);

    // CSR build + graph boundaries (main stream, concurrent with GEMM1)
    k_zero<<<nodeBlocks, 256>>>(batch);
    k_deg<<<edgeBlocks, 256>>>(dst);
    k_build<<<nodeBlocks, 256>>>();
    k_fill<<<edgeBlocks, 256>>>(src, dst);

    // Join: gather1 needs both CSR and GEMM1
    cudaStreamWaitEvent(0, evJoin, 0);
    k_gather<<<gatherBlocks, 256>>>(b1);

    // Layer 2
    k_gemm_tc<<<gemmBlocks, 256, GEMM_SMEM>>>(nullptr, W2, 1);
    k_gather<<<gatherBlocks, 256>>>(b2);

    // Pool + head (fused)
    k_poolhead<<<N_GRAPHS, 128>>>(Wp, bp, out);
}

// round 17
// speedup vs baseline: 1.1417x; 1.1417x over previous
#include <cuda_runtime.h>
#include <cuda_fp16.h>

#define N_NODES 100000
#define N_EDGES 1600000
#define N_GRAPHS 512
#define HID 128

// Scratch (allocation-free rule: __device__ globals; referenced only from device code)
__device__ __half2 g_Ah[(size_t)N_NODES * 64]; // GEMM output (UNscaled), fp16
__device__ __half2 g_Bh[(size_t)N_NODES * 64]; // layer output, fp16
__device__ float g_dis[N_NODES];               // (deg+1)^{-1/2}
__device__ int   g_degi[N_NODES];
__device__ int   g_rowptr[N_NODES];
__device__ int   g_cur[N_NODES];
__device__ int   g_adj[N_EDGES];               // packed CSR (order-free slabs)
__device__ int   g_start[N_GRAPHS];
__device__ int   g_end[N_GRAPHS];
__device__ int   g_total;

// ---------------- zero counters + graph boundaries (fused) ----------------
__global__ void k_zero(const int* __restrict__ batch) {
    int i = blockIdx.x * blockDim.x + threadIdx.x;
    if (i < N_NODES) {
        g_degi[i] = 0;
        unsigned g = (unsigned)batch[i];
        if (g < N_GRAPHS) {
            if (i == 0 || batch[i - 1] != (int)g) g_start[g] = i;
            if (i == N_NODES - 1 || batch[i + 1] != (int)g) g_end[g] = i + 1;
        }
    }
    if (i == 0) g_total = 0;
}

// ---------------- in-degree count over dst ----------------
__global__ void k_deg(const int* __restrict__ dst) {
    int e = blockIdx.x * blockDim.x + threadIdx.x;
    if (e < N_EDGES) {
        unsigned d = (unsigned)dst[e];
        if (d < N_NODES) atomicAdd(&g_degi[d], 1);
    }
}

// ---------------- parallel slab reservation ----------------
__global__ void __launch_bounds__(256) k_build() {
    __shared__ int s[256];
    __shared__ int s_base;
    int t = threadIdx.x;
    int i = blockIdx.x * 256 + t;
    int d = (i < N_NODES) ? g_degi[i] : 0;
    s[t] = d;
    __syncthreads();
    #pragma unroll
    for (int o = 1; o < 256; o <<= 1) {
        int v = (t >= o) ? s[t - o] : 0;
        __syncthreads();
        s[t] += v;
        __syncthreads();
    }
    if (t == 255) s_base = atomicAdd(&g_total, s[255]);
    __syncthreads();
    if (i < N_NODES) {
        int start = s_base + s[t] - d;
        g_rowptr[i] = start;
        g_cur[i] = start;
        g_dis[i] = rsqrtf((float)(d + 1));   // +1 self loop
    }
}

// ---------------- fill adjacency (src grouped by dst) ----------------
__global__ void k_fill(const int* __restrict__ src,
                       const int* __restrict__ dst) {
    int e = blockIdx.x * blockDim.x + threadIdx.x;
    if (e < N_EDGES) {
        unsigned d = (unsigned)dst[e];
        unsigned sv = (unsigned)src[e];
        if (d < N_NODES && sv < N_NODES) {
            int pos = atomicAdd(&g_cur[d], 1);
            g_adj[pos] = (int)sv;
        }
    }
}

// ---------------- TF32 tensor-core GEMM: g_Ah[row] = fp16(In[row]@W) (no dis) --------
#define A_STRIDE 132
#define W_STRIDE 136
#define GEMM_SMEM ((64 * A_STRIDE + 128 * W_STRIDE) * 4)

__device__ __forceinline__ float tf32r(float x) {
    float y;
    asm("cvt.rna.tf32.f32 %0, %1;" : "=f"(y) : "f"(x));
    return y;
}

__global__ void __launch_bounds__(256) k_gemm_tc(const float* __restrict__ X,
                                                 const float* __restrict__ W,
                                                 int useB) {
    extern __shared__ float smem[];
    float* sA = smem;                    // [64][132]
    float* sW = smem + 64 * A_STRIDE;    // [128][136]

    const int tid = threadIdx.x;
    const int lane = tid & 31;
    const int wid = tid >> 5;
    const int warpM = wid >> 2;          // 0..1
    const int warpN = wid & 3;           // 0..3
    const int g = lane >> 2;             // 0..7
    const int t = lane & 3;              // 0..3
    const int rowBase = blockIdx.x * 64;

    #pragma unroll
    for (int l = tid; l < 2048; l += 256) {
        int r = l >> 5, c4 = (l & 31) * 4;
        int row = rowBase + r;
        float4 v = make_float4(0.f, 0.f, 0.f, 0.f);
        if (row < N_NODES) {
            if (useB) {
                uint2 u = ((const uint2*)g_Bh)[(size_t)row * 32 + (l & 31)];
                float2 f0 = __half22float2(*(__half2*)&u.x);
                float2 f1 = __half22float2(*(__half2*)&u.y);
                v = make_float4(f0.x, f0.y, f1.x, f1.y);
            } else {
                v = *(const float4*)(X + (size_t)row * 128 + c4);
            }
        }
        float* p = &sA[r * A_STRIDE + c4];
        p[0] = tf32r(v.x); p[1] = tf32r(v.y); p[2] = tf32r(v.z); p[3] = tf32r(v.w);
    }
    #pragma unroll
    for (int l = tid; l < 4096; l += 256) {
        int r = l >> 5, c4 = (l & 31) * 4;
        float4 v = *(const float4*)(W + (size_t)r * 128 + c4);
        float* p = &sW[r * W_STRIDE + c4];
        p[0] = tf32r(v.x); p[1] = tf32r(v.y); p[2] = tf32r(v.z); p[3] = tf32r(v.w);
    }
    __syncthreads();

    float acc[2][4][4];
    #pragma unroll
    for (int mi = 0; mi < 2; mi++)
        #pragma unroll
        for (int ni = 0; ni < 4; ni++)
            #pragma unroll
            for (int k = 0; k < 4; k++) acc[mi][ni][k] = 0.f;

    #pragma unroll
    for (int k0 = 0; k0 < 128; k0 += 8) {
        unsigned a[2][4];
        #pragma unroll
        for (int mi = 0; mi < 2; mi++) {
            int rlo = (warpM * 32 + mi * 16 + g) * A_STRIDE;
            int rhi = rlo + 8 * A_STRIDE;
            a[mi][0] = __float_as_uint(sA[rlo + k0 + t]);
            a[mi][1] = __float_as_uint(sA[rhi + k0 + t]);
            a[mi][2] = __float_as_uint(sA[rlo + k0 + t + 4]);
            a[mi][3] = __float_as_uint(sA[rhi + k0 + t + 4]);
        }
        #pragma unroll
        for (int ni = 0; ni < 4; ni++) {
            int n = warpN * 32 + ni * 8 + g;
            unsigned b0 = __float_as_uint(sW[(k0 + t) * W_STRIDE + n]);
            unsigned b1 = __float_as_uint(sW[(k0 + t + 4) * W_STRIDE + n]);
            #pragma unroll
            for (int mi = 0; mi < 2; mi++) {
                asm volatile(
                    "mma.sync.aligned.m16n8k8.row.col.f32.tf32.tf32.f32 "
                    "{%0,%1,%2,%3}, {%4,%5,%6,%7}, {%8,%9}, {%0,%1,%2,%3};"
                    : "+f"(acc[mi][ni][0]), "+f"(acc[mi][ni][1]),
                      "+f"(acc[mi][ni][2]), "+f"(acc[mi][ni][3])
                    : "r"(a[mi][0]), "r"(a[mi][1]), "r"(a[mi][2]), "r"(a[mi][3]),
                      "r"(b0), "r"(b1));
            }
        }
    }

    // ---- epilogue: convert to fp16 (unscaled), store half2 ----
    #pragma unroll
    for (int mi = 0; mi < 2; mi++) {
        int rlo = rowBase + warpM * 32 + mi * 16 + g;
        int rhi = rlo + 8;
        #pragma unroll
        for (int ni = 0; ni < 4; ni++) {
            int h2idx = warpN * 16 + ni * 4 + t;
            if (rlo < N_NODES)
                g_Ah[(size_t)rlo * 64 + h2idx] =
                    __floats2half2_rn(acc[mi][ni][0], acc[mi][ni][1]);
            if (rhi < N_NODES)
                g_Ah[(size_t)rhi * 64 + h2idx] =
                    __floats2half2_rn(acc[mi][ni][2], acc[mi][ni][3]);
        }
    }
}

// ---------------- gather + finalize: one warp per dst node (no atomics) ----------------
// g_Bh[d] = fp16(relu(dis_d * (dis_d*h_d + sum_s dis_s*h_s) + bias)), fp32 accumulate.
__device__ __forceinline__ float4 h2f4(uint2 u) {
    float2 f0 = __half22float2(*(__half2*)&u.x);
    float2 f1 = __half22float2(*(__half2*)&u.y);
    return make_float4(f0.x, f0.y, f1.x, f1.y);
}

__global__ void k_gather(const float* __restrict__ bias) {
    int node = (blockIdx.x * blockDim.x + threadIdx.x) >> 5;
    if (node >= N_NODES) return;
    const int lane = threadIdx.x & 31;
    const uint2* A = (const uint2*)g_Ah;
    const float sc = g_dis[node];

    float4 self = h2f4(A[(size_t)node * 32 + lane]);
    float4 a0, a1, a2, a3;
    a0 = make_float4(self.x * sc, self.y * sc, self.z * sc, self.w * sc);
    a1 = make_float4(0.f, 0.f, 0.f, 0.f);
    a2 = make_float4(0.f, 0.f, 0.f, 0.f);
    a3 = make_float4(0.f, 0.f, 0.f, 0.f);

    int r0 = g_rowptr[node];
    int r1 = r0 + g_degi[node];
    int i = r0;
    for (; i + 3 < r1; i += 4) {
        int s0 = g_adj[i], s1 = g_adj[i + 1], s2 = g_adj[i + 2], s3 = g_adj[i + 3];
        float d0 = g_dis[s0], d1 = g_dis[s1], d2 = g_dis[s2], d3 = g_dis[s3];
        float4 v0 = h2f4(A[(size_t)s0 * 32 + lane]);
        float4 v1 = h2f4(A[(size_t)s1 * 32 + lane]);
        float4 v2 = h2f4(A[(size_t)s2 * 32 + lane]);
        float4 v3 = h2f4(A[(size_t)s3 * 32 + lane]);
        a0.x = fmaf(v0.x, d0, a0.x); a0.y = fmaf(v0.y, d0, a0.y);
        a0.z = fmaf(v0.z, d0, a0.z); a0.w = fmaf(v0.w, d0, a0.w);
        a1.x = fmaf(v1.x, d1, a1.x); a1.y = fmaf(v1.y, d1, a1.y);
        a1.z = fmaf(v1.z, d1, a1.z); a1.w = fmaf(v1.w, d1, a1.w);
        a2.x = fmaf(v2.x, d2, a2.x); a2.y = fmaf(v2.y, d2, a2.y);
        a2.z = fmaf(v2.z, d2, a2.z); a2.w = fmaf(v2.w, d2, a2.w);
        a3.x = fmaf(v3.x, d3, a3.x); a3.y = fmaf(v3.y, d3, a3.y);
        a3.z = fmaf(v3.z, d3, a3.z); a3.w = fmaf(v3.w, d3, a3.w);
    }
    for (; i < r1; i++) {
        int s0 = g_adj[i];
        float d0 = g_dis[s0];
        float4 v0 = h2f4(A[(size_t)s0 * 32 + lane]);
        a0.x = fmaf(v0.x, d0, a0.x); a0.y = fmaf(v0.y, d0, a0.y);
        a0.z = fmaf(v0.z, d0, a0.z); a0.w = fmaf(v0.w, d0, a0.w);
    }
    a0.x += a1.x + a2.x + a3.x;
    a0.y += a1.y + a2.y + a3.y;
    a0.z += a1.z + a2.z + a3.z;
    a0.w += a1.w + a2.w + a3.w;

    float4 bi = ((const float4*)bias)[lane];
    float rx = fmaxf(fmaf(a0.x, sc, bi.x), 0.f);
    float ry = fmaxf(fmaf(a0.y, sc, bi.y), 0.f);
    float rz = fmaxf(fmaf(a0.z, sc, bi.z), 0.f);
    float rw = fmaxf(fmaf(a0.w, sc, bi.w), 0.f);

    uint2 o;
    *(__half2*)&o.x = __floats2half2_rn(rx, ry);
    *(__half2*)&o.y = __floats2half2_rn(rz, rw);
    ((uint2*)g_Bh)[(size_t)node * 32 + lane] = o;
}

// ---------------- fused pool + head: block per graph ----------------
__global__ void __launch_bounds__(128) k_poolhead(const float* __restrict__ Wp,
                                                  const float* __restrict__ bp,
                                                  float* __restrict__ out) {
    __shared__ float sred[128];
    int g = blockIdx.x;
    int c = threadIdx.x;
    int s = g_start[g], e = g_end[g];
    const __half* Bh = (const __half*)g_Bh;
    float sum = 0.f;
    for (int r = s; r < e; r++)
        sum += __half2float(Bh[(size_t)r * 128 + c]);
    sred[c] = sum * Wp[c];
    __syncthreads();
    #pragma unroll
    for (int o = 64; o; o >>= 1) {
        if (c < o) sred[c] += sred[c + o];
        __syncthreads();
    }
    if (c == 0) {
        float cnt = (float)(e - s);
        out[g] = sred[0] / fmaxf(cnt, 1.0f) + bp[0];
    }
}

extern "C" void kernel_launch(void* const* d_in, const int* in_sizes, int n_in,
                              void* d_out, int out_size) {
    const float* x     = (const float*)d_in[0];
    const int*   ei    = (const int*)d_in[1];      // [2, E] int32
    const int*   batch = (const int*)d_in[2];      // int32
    const float* W1    = (const float*)d_in[3];
    const float* b1    = (const float*)d_in[4];
    const float* W2    = (const float*)d_in[5];
    const float* b2    = (const float*)d_in[6];
    const float* Wp    = (const float*)d_in[7];
    const float* bp    = (const float*)d_in[8];
    float* out = (float*)d_out;

    const int* src = ei;
    const int* dst = ei + N_EDGES;

    const int nodeBlocks   = (N_NODES + 255) / 256;
    const int edgeBlocks   = (N_EDGES + 255) / 256;
    const int gemmBlocks   = (N_NODES + 63) / 64;
    const int gatherBlocks = (N_NODES * 32 + 255) / 256;

    // One-time infra (created on first call, before graph capture)
    static cudaStream_t s2 = nullptr;
    static cudaEvent_t evFork = nullptr, evJoin = nullptr;
    static bool initDone = false;
    if (!initDone) {
        cudaFuncSetAttribute(k_gemm_tc, cudaFuncAttributeMaxDynamicSharedMemorySize,
                             GEMM_SMEM);
        cudaStreamCreateWithFlags(&s2, cudaStreamNonBlocking);
        cudaEventCreateWithFlags(&evFork, cudaEventDisableTiming);
        cudaEventCreateWithFlags(&evJoin, cudaEventDisableTiming);
        initDone = true;
    }

    // Fork: GEMM1 (independent of CSR build — dis applied in gather)
    cudaEventRecord(evFork, 0);
    cudaStreamWaitEvent(s2, evFork, 0);
    k_gemm_tc<<<gemmBlocks, 256, GEMM_SMEM, s2>>>(x, W1, 0);
    cudaEventRecord(evJoin, s2);

    // CSR build + graph boundaries (main stream, concurrent with GEMM1)
    k_zero<<<nodeBlocks, 256>>>(batch);
    k_deg<<<edgeBlocks, 256>>>(dst);
    k_build<<<nodeBlocks, 256>>>();
    k_fill<<<edgeBlocks, 256>>>(src, dst);

    // Join: gather1 needs both CSR and GEMM1
    cudaStreamWaitEvent(0, evJoin, 0);
    k_gather<<<gatherBlocks, 256>>>(b1);

    // Layer 2
    k_gemm_tc<<<gemmBlocks, 256, GEMM_SMEM>>>(nullptr, W2, 1);
    k_gather<<<gatherBlocks, 256>>>(b2);

    // Pool + head (fused)
    k_poolhead<<<N_GRAPHS, 128>>>(Wp, bp, out);
}